// round 2
// baseline (speedup 1.0000x reference)
#include <cuda_runtime.h>
#include <cstdint>

#define EPSV 1e-5f
#define B_   4
#define C_   96
#define HW   4096
#define OCT  166     // 18 + 50 + 98 offset channels
#define OCP  192     // padded
#define KK   864     // 96*9
#define CC3  288
#define O_   192

// ---------------- scratch (static device globals; no dynamic alloc) ----------
__device__ float g_off[B_ * OCT * HW];   // offset conv output  [b][oc][p]
__device__ float g_xc [B_ * CC3 * HW];   // concat deform output [b][c][p]
__device__ float g_wT [KK * OCP];        // packed offset weights, [c*9+r][oc]
__device__ float g_bo [OCP];             // packed offset bias
__device__ float g_pwT[CC3 * O_];        // pointwise weights transposed [c][o]

// ---------------- prep: pack/transpose weights --------------------------------
__global__ void prep_kernel(const float* __restrict__ w3, const float* __restrict__ b3,
                            const float* __restrict__ w5, const float* __restrict__ b5,
                            const float* __restrict__ w7, const float* __restrict__ b7,
                            const float* __restrict__ wpw) {
    int i0 = blockIdx.x * blockDim.x + threadIdx.x;
    int stride = gridDim.x * blockDim.x;
    for (int idx = i0; idx < KK * OCP; idx += stride) {
        int k = idx / OCP, oc = idx % OCP;
        int c = k / 9, r = k % 9;
        float v = 0.f;
        if (oc < 18)        v = w3[(oc * C_ + c) * 9 + r];
        else if (oc < 68)   v = w5[((oc - 18) * C_ + c) * 9 + r];
        else if (oc < OCT)  v = w7[((oc - 68) * C_ + c) * 9 + r];
        g_wT[idx] = v;
    }
    for (int idx = i0; idx < OCP; idx += stride) {
        float v = 0.f;
        if (idx < 18)       v = b3[idx];
        else if (idx < 68)  v = b5[idx - 18];
        else if (idx < OCT) v = b7[idx - 68];
        g_bo[idx] = v;
    }
    for (int idx = i0; idx < CC3 * O_; idx += stride) {
        int c = idx / O_, o = idx % O_;
        g_pwT[idx] = wpw[o * CC3 + c];
    }
}

// ---------------- K1: fused 3x3 offset conv (all 166 out channels) ------------
// grid (32 pixel tiles of 2 rows, 3 oc-tiles of 64, 4 batch), 128 threads,
// each thread computes an 8oc x 8px register tile.
__global__ __launch_bounds__(128) void offconv_kernel(const float* __restrict__ x) {
    __shared__ float s_in[8][4][66];
    __shared__ float s_w[8][9][64];
    int tid = threadIdx.x;
    int pxg = tid & 15, ocg = tid >> 4;          // 16 pixel groups, 8 oc groups
    int b = blockIdx.z, ocb = blockIdx.y * 64;
    int r0 = blockIdx.x * 2;
    int prow = pxg >> 3, pcol = (pxg & 7) * 8;

    float acc[64];
#pragma unroll
    for (int i = 0; i < 64; i++) acc[i] = 0.f;
    const float* xb = x + (size_t)b * C_ * HW;

    for (int ch = 0; ch < 12; ++ch) {
        int c0 = ch * 8;
        __syncthreads();
        for (int idx = tid; idx < 8 * 4 * 66; idx += 128) {
            int cc = idx / 264, rem = idx % 264;
            int row = rem / 66, col = rem % 66;
            int gy = r0 - 1 + row, gx = col - 1;
            float v = 0.f;
            if ((unsigned)gy < 64u && (unsigned)gx < 64u)
                v = xb[(c0 + cc) * HW + gy * 64 + gx];
            s_in[cc][row][col] = v;
        }
        for (int idx = tid; idx < 8 * 9 * 64; idx += 128) {
            int cc = idx / 576, rem = idx % 576;
            int r = rem / 64, oc = rem % 64;
            s_w[cc][r][oc] = g_wT[((c0 + cc) * 9 + r) * OCP + ocb + oc];
        }
        __syncthreads();
#pragma unroll 1
        for (int cc = 0; cc < 8; ++cc) {
#pragma unroll
            for (int ky = 0; ky < 3; ++ky) {
                float win[10];
                const float* rp = &s_in[cc][prow + ky][pcol];
#pragma unroll
                for (int i = 0; i < 10; i++) win[i] = rp[i];
#pragma unroll
                for (int kx = 0; kx < 3; kx++) {
                    const float* wp = &s_w[cc][ky * 3 + kx][ocg * 8];
                    float w8[8];
#pragma unroll
                    for (int i = 0; i < 8; i++) w8[i] = wp[i];
#pragma unroll
                    for (int i = 0; i < 8; i++)
#pragma unroll
                        for (int j = 0; j < 8; j++)
                            acc[i * 8 + j] = fmaf(w8[i], win[kx + j], acc[i * 8 + j]);
                }
            }
        }
    }
    int py = r0 + prow;
#pragma unroll
    for (int i = 0; i < 8; i++) {
        int oc = ocb + ocg * 8 + i;
        if (oc < OCT) {
            float bias = g_bo[oc];
            float* op = g_off + ((size_t)b * OCT + oc) * HW + py * 64 + pcol;
#pragma unroll
            for (int j = 0; j < 8; j++) op[j] = acc[i * 8 + j] + bias;
        }
    }
}

// ---------------- K2: deformable depthwise + BN + ReLU ------------------------
// grid (16 pixtiles of 256px, 4 channel-splits, 4 batch), 256 threads, 1 px/thread.
// 6 full 64x64 x-planes resident in smem per channel-group; the per-pixel tap
// plan (offsets + bilinear weights) is computed once and reused for 6 channels.
#define PLSTRIDE 4164   // 4096 plane + 68 zero pad (clipped corners read finite 0)
template<int K2T, int KT, int SB, int SIDX>
__global__ __launch_bounds__(256) void deform_kernel(
    const float* __restrict__ x, const float* __restrict__ wdw,
    const float* __restrict__ gg, const float* __restrict__ bb,
    const float* __restrict__ mm, const float* __restrict__ vv) {
    extern __shared__ float sm[];
    float* planes = sm;                 // 6 * PLSTRIDE
    float* wdw_s  = sm + 6 * PLSTRIDE;  // 6 * 49
    int tid = threadIdx.x;
    int b = blockIdx.z;
    int p = blockIdx.x * 256 + tid;
    float yf = (float)(p >> 6), xf = (float)(p & 63);
    const float* offb = g_off + ((size_t)b * OCT + SB) * HW + p;
    const float* xb = x + (size_t)b * C_ * HW;

    // zero the pads once (never overwritten later)
    for (int i = tid; i < 6 * 68; i += 256) {
        int ci = i / 68;
        planes[ci * PLSTRIDE + 4096 + (i % 68)] = 0.f;
    }

    for (int it = 0; it < 4; ++it) {
        int cbase = (blockIdx.y * 4 + it) * 6;
        __syncthreads();   // pad init (iter 0) / previous compute done
        for (int i = tid; i < 6 * 1024; i += 256) {
            int ci = i >> 10, j = i & 1023;
            float4 v = *(const float4*)(xb + (size_t)(cbase + ci) * HW + j * 4);
            *(float4*)(planes + ci * PLSTRIDE + j * 4) = v;
        }
        for (int i = tid; i < 6 * K2T; i += 256) {
            int ci = i / K2T, t = i % K2T;
            wdw_s[ci * 49 + t] = wdw[(cbase + ci) * K2T + t];
        }
        __syncthreads();

        float acc[6];
#pragma unroll
        for (int ci = 0; ci < 6; ci++) acc[ci] = 0.f;

        int t = 0;
#pragma unroll 1
        for (int ty = 0; ty < KT; ++ty) {
            float pny = (float)(ty - (KT - 1) / 2);
#pragma unroll
            for (int tx = 0; tx < KT; ++tx, ++t) {
                float pnx = (float)(tx - (KT - 1) / 2);
                float dy = __ldg(offb + (size_t)t * HW);
                float dx = __ldg(offb + (size_t)(K2T + t) * HW);
                float py = fminf(fmaxf(yf + pny + dy, 0.f), 63.f);
                float px = fminf(fmaxf(xf + pnx + dx, 0.f), 63.f);
                float fy = floorf(py), fx = floorf(px);
                float wy = py - fy, wx = px - fx;
                int idx = (int)fy * 64 + (int)fx;
                float w1y = 1.f - wy, w1x = 1.f - wx;
                float w00 = w1y * w1x, w01 = w1y * wx;
                float w10 = wy * w1x,  w11 = wy * wx;
#pragma unroll
                for (int ci = 0; ci < 6; ci++) {
                    const float* pl = planes + ci * PLSTRIDE + idx;
                    float v = w00 * pl[0] + w01 * pl[1] + w10 * pl[64] + w11 * pl[65];
                    acc[ci] = fmaf(wdw_s[ci * 49 + t], v, acc[ci]);
                }
            }
        }
#pragma unroll
        for (int ci = 0; ci < 6; ci++) {
            int c = cbase + ci;
            float inv = __ldg(gg + c) * rsqrtf(__ldg(vv + c) + EPSV);
            float sh  = __ldg(bb + c) - __ldg(mm + c) * inv;
            float val = fmaxf(fmaf(acc[ci], inv, sh), 0.f);
            g_xc[((size_t)b * CC3 + SIDX * 96 + c) * HW + p] = val;
        }
    }
}

// ---------------- K3: pointwise 288->192 GEMM + BN + ReLU ---------------------
// grid (32 pixtiles of 128, 3 oc-tiles of 64, 4 batch), 128 threads, 8x8 tiles
__global__ __launch_bounds__(128) void pw_kernel(
    const float* __restrict__ gp, const float* __restrict__ bp,
    const float* __restrict__ mp, const float* __restrict__ vp,
    float* __restrict__ out) {
    __shared__ float s_x[8][128];
    __shared__ float s_w[8][64];
    int tid = threadIdx.x;
    int pxg = tid & 15, ocg = tid >> 4;
    int b = blockIdx.z, ocb = blockIdx.y * 64, p0 = blockIdx.x * 128;

    float acc[64];
#pragma unroll
    for (int i = 0; i < 64; i++) acc[i] = 0.f;
    const float* xcb = g_xc + (size_t)b * CC3 * HW + p0;

    for (int ch = 0; ch < 36; ++ch) {
        int c0 = ch * 8;
        __syncthreads();
        for (int i = tid; i < 1024; i += 128) {
            int cc = i >> 7, pp = i & 127;
            s_x[cc][pp] = xcb[(size_t)(c0 + cc) * HW + pp];
        }
        for (int i = tid; i < 512; i += 128) {
            int cc = i >> 6, oc = i & 63;
            s_w[cc][oc] = g_pwT[(c0 + cc) * O_ + ocb + oc];
        }
        __syncthreads();
#pragma unroll
        for (int cc = 0; cc < 8; ++cc) {
            float x8[8], w8[8];
            *(float4*)&x8[0] = *(float4*)&s_x[cc][pxg * 8];
            *(float4*)&x8[4] = *(float4*)&s_x[cc][pxg * 8 + 4];
            *(float4*)&w8[0] = *(float4*)&s_w[cc][ocg * 8];
            *(float4*)&w8[4] = *(float4*)&s_w[cc][ocg * 8 + 4];
#pragma unroll
            for (int i = 0; i < 8; i++)
#pragma unroll
                for (int j = 0; j < 8; j++)
                    acc[i * 8 + j] = fmaf(w8[i], x8[j], acc[i * 8 + j]);
        }
    }
#pragma unroll
    for (int i = 0; i < 8; i++) {
        int oc = ocb + ocg * 8 + i;
        float inv = __ldg(gp + oc) * rsqrtf(__ldg(vp + oc) + EPSV);
        float sh  = __ldg(bp + oc) - __ldg(mp + oc) * inv;
        float* op = out + ((size_t)b * O_ + oc) * HW + p0 + pxg * 8 - pxg * 8; // base
        op += 0;
#pragma unroll
        for (int j = 0; j < 8; j++) {
            int pp = p0 + pxg * 8 + j - p0; // local
            out[((size_t)b * O_ + oc) * HW + p0 + pxg * 8 + j] =
                fmaxf(fmaf(acc[i * 8 + j], inv, sh), 0.f);
        }
    }
}

// ---------------- launch ------------------------------------------------------
extern "C" void kernel_launch(void* const* d_in, const int* in_sizes, int n_in,
                              void* d_out, int out_size) {
    const float* x     = (const float*)d_in[0];
    const float* w3    = (const float*)d_in[1];
    const float* b3    = (const float*)d_in[2];
    const float* wdw3  = (const float*)d_in[3];
    const float* g3    = (const float*)d_in[4];
    const float* be3   = (const float*)d_in[5];
    const float* m3    = (const float*)d_in[6];
    const float* v3    = (const float*)d_in[7];
    const float* w5    = (const float*)d_in[8];
    const float* b5    = (const float*)d_in[9];
    const float* wdw5  = (const float*)d_in[10];
    const float* g5    = (const float*)d_in[11];
    const float* be5   = (const float*)d_in[12];
    const float* m5    = (const float*)d_in[13];
    const float* v5    = (const float*)d_in[14];
    const float* w7    = (const float*)d_in[15];
    const float* b7    = (const float*)d_in[16];
    const float* wdw7  = (const float*)d_in[17];
    const float* g7    = (const float*)d_in[18];
    const float* be7   = (const float*)d_in[19];
    const float* m7    = (const float*)d_in[20];
    const float* v7    = (const float*)d_in[21];
    const float* wpw   = (const float*)d_in[22];
    const float* gp    = (const float*)d_in[23];
    const float* bp    = (const float*)d_in[24];
    const float* mp    = (const float*)d_in[25];
    const float* vp    = (const float*)d_in[26];
    float* out = (float*)d_out;

    int smem_deform = (6 * PLSTRIDE + 6 * 49) * sizeof(float);
    cudaFuncSetAttribute(deform_kernel<9, 3, 0, 0>,
                         cudaFuncAttributeMaxDynamicSharedMemorySize, smem_deform);
    cudaFuncSetAttribute(deform_kernel<25, 5, 18, 1>,
                         cudaFuncAttributeMaxDynamicSharedMemorySize, smem_deform);
    cudaFuncSetAttribute(deform_kernel<49, 7, 68, 2>,
                         cudaFuncAttributeMaxDynamicSharedMemorySize, smem_deform);

    prep_kernel<<<256, 256>>>(w3, b3, w5, b5, w7, b7, wpw);
    offconv_kernel<<<dim3(32, 3, B_), 128>>>(x);
    deform_kernel<9, 3, 0, 0><<<dim3(16, 4, B_), 256, smem_deform>>>(x, wdw3, g3, be3, m3, v3);
    deform_kernel<25, 5, 18, 1><<<dim3(16, 4, B_), 256, smem_deform>>>(x, wdw5, g5, be5, m5, v5);
    deform_kernel<49, 7, 68, 2><<<dim3(16, 4, B_), 256, smem_deform>>>(x, wdw7, g7, be7, m7, v7);
    pw_kernel<<<dim3(32, 3, B_), 128>>>(gp, bp, mp, vp, out);
}

// round 7
// speedup vs baseline: 1.0847x; 1.0847x over previous
#include <cuda_runtime.h>
#include <cuda_bf16.h>
#include <cstdint>

#define EPSV 1e-5f
#define B_   4
#define C_   96
#define HW   4096
#define OCT  166     // 18 + 50 + 98 offset channels
#define OCP  192     // padded
#define KK   864     // 96*9
#define KP   320     // g_xc row stride (288 used)
#define O_   192

// ---------------- scratch (static device globals) -----------------------------
__device__ float g_off[B_ * OCT * HW];          // offset conv output  [b][oc][p]
__device__ float g_xc [B_ * HW * KP];           // deform output, PIXEL-major [b*HW+p][KP]
__device__ float g_wT [KK * OCP];               // packed offset weights, [c*9+r][oc]
__device__ float g_bo [OCP];                    // packed offset bias
__device__ __nv_bfloat16 g_pwh[O_ * KP];        // pointwise weights hi [o][KP]
__device__ __nv_bfloat16 g_pwl[O_ * KP];        // pointwise weights lo [o][KP]

__device__ __forceinline__ uint32_t smem_u32(const void* p) {
    uint32_t a;
    asm("{ .reg .u64 t; cvta.to.shared.u64 t, %1; cvt.u32.u64 %0, t; }" : "=r"(a) : "l"(p));
    return a;
}
#define LDSM4(r, addr) \
    asm volatile("ldmatrix.sync.aligned.m8n8.x4.shared.b16 {%0,%1,%2,%3}, [%4];" \
        : "=r"((r)[0]), "=r"((r)[1]), "=r"((r)[2]), "=r"((r)[3]) : "r"(addr))
#define LDSM2(r, addr) \
    asm volatile("ldmatrix.sync.aligned.m8n8.x2.shared.b16 {%0,%1}, [%2];" \
        : "=r"((r)[0]), "=r"((r)[1]) : "r"(addr))
#define MMA_BF16(d, a, b) \
    asm volatile("mma.sync.aligned.m16n8k16.row.col.f32.bf16.bf16.f32 " \
        "{%0,%1,%2,%3}, {%4,%5,%6,%7}, {%8,%9}, {%0,%1,%2,%3};" \
        : "+f"((d)[0]), "+f"((d)[1]), "+f"((d)[2]), "+f"((d)[3]) \
        : "r"((a)[0]), "r"((a)[1]), "r"((a)[2]), "r"((a)[3]), "r"((b)[0]), "r"((b)[1]))

// ---------------- prep: pack/transpose weights --------------------------------
__global__ void prep_kernel(const float* __restrict__ w3, const float* __restrict__ b3,
                            const float* __restrict__ w5, const float* __restrict__ b5,
                            const float* __restrict__ w7, const float* __restrict__ b7,
                            const float* __restrict__ wpw) {
    int i0 = blockIdx.x * blockDim.x + threadIdx.x;
    int stride = gridDim.x * blockDim.x;
    for (int idx = i0; idx < KK * OCP; idx += stride) {
        int k = idx / OCP, oc = idx % OCP;
        int c = k / 9, r = k % 9;
        float v = 0.f;
        if (oc < 18)        v = w3[(oc * C_ + c) * 9 + r];
        else if (oc < 68)   v = w5[((oc - 18) * C_ + c) * 9 + r];
        else if (oc < OCT)  v = w7[((oc - 68) * C_ + c) * 9 + r];
        g_wT[idx] = v;
    }
    for (int idx = i0; idx < OCP; idx += stride) {
        float v = 0.f;
        if (idx < 18)       v = b3[idx];
        else if (idx < 68)  v = b5[idx - 18];
        else if (idx < OCT) v = b7[idx - 68];
        g_bo[idx] = v;
    }
    for (int idx = i0; idx < O_ * KP; idx += stride) {
        int n = idx / KP, k = idx % KP;
        float w = (k < 288) ? wpw[n * 288 + k] : 0.f;
        __nv_bfloat16 h = __float2bfloat16(w);
        __nv_bfloat16 l = __float2bfloat16(w - __bfloat162float(h));
        g_pwh[idx] = h;
        g_pwl[idx] = l;
    }
}

// ---------------- K1: fused 3x3 offset conv (166 out channels) ----------------
__global__ __launch_bounds__(128) void offconv_kernel(const float* __restrict__ x) {
    __shared__ float s_in[8][4][66];
    __shared__ float s_w[8][9][64];
    int tid = threadIdx.x;
    int pxg = tid & 15, ocg = tid >> 4;
    int b = blockIdx.z, ocb = blockIdx.y * 64;
    int r0 = blockIdx.x * 2;
    int prow = pxg >> 3, pcol = (pxg & 7) * 8;

    float acc[64];
#pragma unroll
    for (int i = 0; i < 64; i++) acc[i] = 0.f;
    const float* xb = x + (size_t)b * C_ * HW;

    for (int ch = 0; ch < 12; ++ch) {
        int c0 = ch * 8;
        __syncthreads();
        for (int idx = tid; idx < 8 * 4 * 66; idx += 128) {
            int cc = idx / 264, rem = idx % 264;
            int row = rem / 66, col = rem % 66;
            int gy = r0 - 1 + row, gx = col - 1;
            float v = 0.f;
            if ((unsigned)gy < 64u && (unsigned)gx < 64u)
                v = xb[(c0 + cc) * HW + gy * 64 + gx];
            s_in[cc][row][col] = v;
        }
        for (int idx = tid; idx < 8 * 9 * 64; idx += 128) {
            int cc = idx / 576, rem = idx % 576;
            int r = rem / 64, oc = rem % 64;
            s_w[cc][r][oc] = g_wT[((c0 + cc) * 9 + r) * OCP + ocb + oc];
        }
        __syncthreads();
#pragma unroll 1
        for (int cc = 0; cc < 8; ++cc) {
#pragma unroll
            for (int ky = 0; ky < 3; ++ky) {
                float win[10];
                const float* rp = &s_in[cc][prow + ky][pcol];
#pragma unroll
                for (int i = 0; i < 10; i++) win[i] = rp[i];
#pragma unroll
                for (int kx = 0; kx < 3; kx++) {
                    const float* wp = &s_w[cc][ky * 3 + kx][ocg * 8];
                    float w8[8];
#pragma unroll
                    for (int i = 0; i < 8; i++) w8[i] = wp[i];
#pragma unroll
                    for (int i = 0; i < 8; i++)
#pragma unroll
                        for (int j = 0; j < 8; j++)
                            acc[i * 8 + j] = fmaf(w8[i], win[kx + j], acc[i * 8 + j]);
                }
            }
        }
    }
    int py = r0 + prow;
#pragma unroll
    for (int i = 0; i < 8; i++) {
        int oc = ocb + ocg * 8 + i;
        if (oc < OCT) {
            float bias = g_bo[oc];
            float* op = g_off + ((size_t)b * OCT + oc) * HW + py * 64 + pcol;
#pragma unroll
            for (int j = 0; j < 8; j++) op[j] = acc[i * 8 + j] + bias;
        }
    }
}

// ---------------- K2: deformable depthwise + BN + ReLU ------------------------
#define PLSTRIDE 4164   // 4096 plane + 68 zero pad
template<int K2T, int KT, int SB, int SIDX>
__global__ __launch_bounds__(512) void deform_kernel(
    const float* __restrict__ x, const float* __restrict__ wdw,
    const float* __restrict__ gg, const float* __restrict__ bb,
    const float* __restrict__ mm, const float* __restrict__ vv) {
    extern __shared__ float sm[];
    float* planes = sm;                 // 6 * PLSTRIDE
    float* wdw_s  = sm + 6 * PLSTRIDE;  // 6 * 49
    int tid = threadIdx.x;
    int b = blockIdx.z;
    int p = blockIdx.x * 512 + tid;
    float yf = (float)(p >> 6), xf = (float)(p & 63);
    const float* offb = g_off + ((size_t)b * OCT + SB) * HW + p;
    const float* xb = x + (size_t)b * C_ * HW;

    for (int i = tid; i < 6 * 68; i += 512) {
        int ci = i / 68;
        planes[ci * PLSTRIDE + 4096 + (i % 68)] = 0.f;
    }

    for (int it = 0; it < 2; ++it) {
        int cbase = blockIdx.y * 12 + it * 6;
        __syncthreads();
        for (int i = tid; i < 6 * 1024; i += 512) {
            int ci = i >> 10, j = i & 1023;
            float4 v = *(const float4*)(xb + (size_t)(cbase + ci) * HW + j * 4);
            *(float4*)(planes + ci * PLSTRIDE + j * 4) = v;
        }
        for (int i = tid; i < 6 * K2T; i += 512) {
            int ci = i / K2T, t = i % K2T;
            wdw_s[ci * 49 + t] = wdw[(cbase + ci) * K2T + t];
        }
        __syncthreads();

        float acc[6];
#pragma unroll
        for (int ci = 0; ci < 6; ci++) acc[ci] = 0.f;

        int t = 0;
#pragma unroll 1
        for (int ty = 0; ty < KT; ++ty) {
            float pny = (float)(ty - (KT - 1) / 2);
#pragma unroll
            for (int tx = 0; tx < KT; ++tx, ++t) {
                float pnx = (float)(tx - (KT - 1) / 2);
                float dy = __ldg(offb + (size_t)t * HW);
                float dx = __ldg(offb + (size_t)(K2T + t) * HW);
                float py = fminf(fmaxf(yf + pny + dy, 0.f), 63.f);
                float px = fminf(fmaxf(xf + pnx + dx, 0.f), 63.f);
                float fy = floorf(py), fx = floorf(px);
                float wy = py - fy, wx = px - fx;
                int idx = (int)fy * 64 + (int)fx;
                float w1y = 1.f - wy, w1x = 1.f - wx;
                float w00 = w1y * w1x, w01 = w1y * wx;
                float w10 = wy * w1x,  w11 = wy * wx;
#pragma unroll
                for (int ci = 0; ci < 6; ci++) {
                    const float* pl = planes + ci * PLSTRIDE + idx;
                    float v = w00 * pl[0] + w01 * pl[1] + w10 * pl[64] + w11 * pl[65];
                    acc[ci] = fmaf(wdw_s[ci * 49 + t], v, acc[ci]);
                }
            }
        }
        float vals[6];
#pragma unroll
        for (int ci = 0; ci < 6; ci++) {
            int c = cbase + ci;
            float inv = __ldg(gg + c) * rsqrtf(__ldg(vv + c) + EPSV);
            float sh  = __ldg(bb + c) - __ldg(mm + c) * inv;
            vals[ci] = fmaxf(fmaf(acc[ci], inv, sh), 0.f);
        }
        float* row = g_xc + ((size_t)b * HW + p) * KP + SIDX * 96 + cbase;
        *(float2*)(row + 0) = make_float2(vals[0], vals[1]);
        *(float2*)(row + 2) = make_float2(vals[2], vals[3]);
        *(float2*)(row + 4) = make_float2(vals[4], vals[5]);
    }
}

// ---------------- K3: pointwise GEMM via mma.sync bf16 2-split + BN + ReLU ----
// 128 blocks (one per 128-px tile), 256 threads = 8 warps (4M x 2N).
// Block tile: M=128 px, N=192 oc, K=288 in 9 chunks of 32.
// smem rows are 56 bf16 = 112 B (16B-aligned, bank-spread across 8 rows).
#define ST    56
#define A_HI  0
#define A_LO  14336
#define B_HI  28672
#define B_LO  50176
#define PW_SMEM 71680

__global__ __launch_bounds__(256) void pw_mma_kernel(
    const float* __restrict__ gp, const float* __restrict__ bp,
    const float* __restrict__ mp, const float* __restrict__ vp,
    float* __restrict__ out) {
    extern __shared__ char dsm[];
    uint32_t sbase = smem_u32(dsm);
    int tid = threadIdx.x, w = tid >> 5, lane = tid & 31;
    int m0 = (w & 3) * 32, n0 = (w >> 2) * 96;
    int P0 = blockIdx.x * 128;
    const float* xrow = g_xc + (size_t)P0 * KP;

    float acc[2][12][4];
#pragma unroll
    for (int i = 0; i < 2; i++)
#pragma unroll
        for (int j = 0; j < 12; j++)
#pragma unroll
            for (int q = 0; q < 4; q++) acc[i][j][q] = 0.f;

    for (int kc = 0; kc < 9; ++kc) {
        __syncthreads();
        // stage A: 128 px x 32 k fp32 -> bf16 hi/lo
        for (int i = tid; i < 1024; i += 256) {
            int px = i >> 3, k4 = (i & 7) * 4;
            float4 v = *(const float4*)(xrow + (size_t)px * KP + kc * 32 + k4);
            __nv_bfloat16 h0 = __float2bfloat16(v.x), h1 = __float2bfloat16(v.y);
            __nv_bfloat16 h2 = __float2bfloat16(v.z), h3 = __float2bfloat16(v.w);
            __nv_bfloat16 l0 = __float2bfloat16(v.x - __bfloat162float(h0));
            __nv_bfloat16 l1 = __float2bfloat16(v.y - __bfloat162float(h1));
            __nv_bfloat16 l2 = __float2bfloat16(v.z - __bfloat162float(h2));
            __nv_bfloat16 l3 = __float2bfloat16(v.w - __bfloat162float(h3));
            uint2 hv, lv;
            hv.x = ((uint32_t)__bfloat16_as_ushort(h1) << 16) | __bfloat16_as_ushort(h0);
            hv.y = ((uint32_t)__bfloat16_as_ushort(h3) << 16) | __bfloat16_as_ushort(h2);
            lv.x = ((uint32_t)__bfloat16_as_ushort(l1) << 16) | __bfloat16_as_ushort(l0);
            lv.y = ((uint32_t)__bfloat16_as_ushort(l3) << 16) | __bfloat16_as_ushort(l2);
            int off = (px * ST + k4) * 2;
            *(uint2*)(dsm + A_HI + off) = hv;
            *(uint2*)(dsm + A_LO + off) = lv;
        }
        // stage B: 192 oc x 32 k bf16 hi/lo (already split in prep)
        for (int i = tid; i < 3072; i += 256) {
            int buf = i >= 1536;
            int r = i - buf * 1536;
            int n = r >> 3, k4 = (r & 7) * 4;
            uint2 v = *(const uint2*)((buf ? g_pwl : g_pwh) + n * KP + kc * 32 + k4);
            *(uint2*)(dsm + (buf ? B_LO : B_HI) + (n * ST + k4) * 2) = v;
        }
        __syncthreads();

#pragma unroll
        for (int ks = 0; ks < 2; ++ks) {
            uint32_t ah[2][4], al[2][4];
            int arow = m0 + (lane & 15);
            int akcol = ks * 16 + (lane >> 4) * 8;
#pragma unroll
            for (int mt = 0; mt < 2; ++mt) {
                uint32_t aaddr = sbase + A_HI + (uint32_t)(((arow + mt * 16) * ST + akcol) * 2);
                LDSM4(ah[mt], aaddr);
                LDSM4(al[mt], aaddr + (A_LO - A_HI));
            }
            int brow = n0 + (lane & 7);
            int bk = ks * 16 + ((lane >> 3) & 1) * 8;
#pragma unroll
            for (int nt = 0; nt < 12; ++nt) {
                uint32_t baddr = sbase + B_HI + (uint32_t)(((brow + nt * 8) * ST + bk) * 2);
                uint32_t bh[2], bl[2];
                LDSM2(bh, baddr);
                LDSM2(bl, baddr + (B_LO - B_HI));
#pragma unroll
                for (int mt = 0; mt < 2; ++mt) {
                    MMA_BF16(acc[mt][nt], ah[mt], bh);
                    MMA_BF16(acc[mt][nt], ah[mt], bl);
                    MMA_BF16(acc[mt][nt], al[mt], bh);
                }
            }
        }
    }
    __syncthreads();

    // epilogue: per-warp smem transpose (stride 36 floats, conflict-free), BN+ReLU
    float* eps = (float*)(dsm) + w * 8 * 36;
    int b = P0 >> 12;
    int pbase = (P0 & 4095) + m0;
    int rq = lane >> 2, cq = (lane & 3) * 2;
#pragma unroll 1
    for (int nt = 0; nt < 12; ++nt) {
#pragma unroll
        for (int mt = 0; mt < 2; ++mt) {
            eps[(cq + 0) * 36 + mt * 16 + rq]     = acc[mt][nt][0];
            eps[(cq + 1) * 36 + mt * 16 + rq]     = acc[mt][nt][1];
            eps[(cq + 0) * 36 + mt * 16 + rq + 8] = acc[mt][nt][2];
            eps[(cq + 1) * 36 + mt * 16 + rq + 8] = acc[mt][nt][3];
        }
        __syncwarp();
#pragma unroll
        for (int oi = 0; oi < 8; ++oi) {
            int oc = n0 + nt * 8 + oi;
            float inv = __ldg(gp + oc) * rsqrtf(__ldg(vp + oc) + EPSV);
            float sh  = __ldg(bp + oc) - __ldg(mp + oc) * inv;
            float v = eps[oi * 36 + lane];
            out[((size_t)b * O_ + oc) * HW + pbase + lane] = fmaxf(fmaf(v, inv, sh), 0.f);
        }
        __syncwarp();
    }
}

// ---------------- launch ------------------------------------------------------
extern "C" void kernel_launch(void* const* d_in, const int* in_sizes, int n_in,
                              void* d_out, int out_size) {
    const float* x     = (const float*)d_in[0];
    const float* w3    = (const float*)d_in[1];
    const float* b3    = (const float*)d_in[2];
    const float* wdw3  = (const float*)d_in[3];
    const float* g3    = (const float*)d_in[4];
    const float* be3   = (const float*)d_in[5];
    const float* m3    = (const float*)d_in[6];
    const float* v3    = (const float*)d_in[7];
    const float* w5    = (const float*)d_in[8];
    const float* b5    = (const float*)d_in[9];
    const float* wdw5  = (const float*)d_in[10];
    const float* g5    = (const float*)d_in[11];
    const float* be5   = (const float*)d_in[12];
    const float* m5    = (const float*)d_in[13];
    const float* v5    = (const float*)d_in[14];
    const float* w7    = (const float*)d_in[15];
    const float* b7    = (const float*)d_in[16];
    const float* wdw7  = (const float*)d_in[17];
    const float* g7    = (const float*)d_in[18];
    const float* be7   = (const float*)d_in[19];
    const float* m7    = (const float*)d_in[20];
    const float* v7    = (const float*)d_in[21];
    const float* wpw   = (const float*)d_in[22];
    const float* gp    = (const float*)d_in[23];
    const float* bp    = (const float*)d_in[24];
    const float* mp    = (const float*)d_in[25];
    const float* vp    = (const float*)d_in[26];
    float* out = (float*)d_out;

    int smem_deform = (6 * PLSTRIDE + 6 * 49) * sizeof(float);
    cudaFuncSetAttribute(deform_kernel<9, 3, 0, 0>,
                         cudaFuncAttributeMaxDynamicSharedMemorySize, smem_deform);
    cudaFuncSetAttribute(deform_kernel<25, 5, 18, 1>,
                         cudaFuncAttributeMaxDynamicSharedMemorySize, smem_deform);
    cudaFuncSetAttribute(deform_kernel<49, 7, 68, 2>,
                         cudaFuncAttributeMaxDynamicSharedMemorySize, smem_deform);
    cudaFuncSetAttribute(pw_mma_kernel,
                         cudaFuncAttributeMaxDynamicSharedMemorySize, PW_SMEM);

    prep_kernel<<<256, 256>>>(w3, b3, w5, b5, w7, b7, wpw);
    offconv_kernel<<<dim3(32, 3, B_), 128>>>(x);
    deform_kernel<9, 3, 0, 0><<<dim3(8, 8, B_), 512, smem_deform>>>(x, wdw3, g3, be3, m3, v3);
    deform_kernel<25, 5, 18, 1><<<dim3(8, 8, B_), 512, smem_deform>>>(x, wdw5, g5, be5, m5, v5);
    deform_kernel<49, 7, 68, 2><<<dim3(8, 8, B_), 512, smem_deform>>>(x, wdw7, g7, be7, m7, v7);
    pw_mma_kernel<<<128, 256, PW_SMEM>>>(gp, bp, mp, vp, out);
}